// round 1
// baseline (speedup 1.0000x reference)
#include <cuda_runtime.h>
#include <cuda_bf16.h>
#include <math.h>

// ---------------- problem constants ----------------
#define Bb 2
#define Tt 2048
#define Dd 1024
#define Hh 8
#define DK 128
#define DV 256
#define NH 2
#define INTER 2816
#define BT (Bb*Tt)              // 4096

// ---------------- scratch (device globals; no allocation allowed) ----------
__device__ float g_x   [(size_t)BT*Dd];
__device__ float g_qpre[(size_t)BT*Hh*DK];
__device__ float g_kpre[(size_t)BT*NH*Hh*DK];
__device__ float g_vpre[(size_t)BT*NH*Hh*DV];
__device__ float g_q   [(size_t)BT*Hh*DK];
__device__ float g_k   [(size_t)BT*NH*Hh*DK];
__device__ float g_v   [(size_t)BT*NH*Hh*DV];
__device__ float g_gate[(size_t)BT*Hh*DV];
__device__ float g_beta[(size_t)BT*Hh*NH];
__device__ float g_gdec[(size_t)BT*Hh];
__device__ float g_o   [(size_t)BT*Hh*DV];
__device__ float g_hid [(size_t)BT*Dd];
__device__ float g_y   [(size_t)BT*Dd];
__device__ float g_gu  [(size_t)BT*2*INTER];
__device__ float g_mlp [(size_t)BT*INTER];

// ---------------- helpers ----------------
__device__ __forceinline__ float sigmoidf_(float x){ return 1.f/(1.f+expf(-x)); }
__device__ __forceinline__ float siluf_(float x){ return x*sigmoidf_(x); }

__device__ __forceinline__ float block_reduce_sum(float v, float* sh){
    int lane = threadIdx.x & 31, warp = threadIdx.x >> 5;
    #pragma unroll
    for (int m=16;m;m>>=1) v += __shfl_xor_sync(0xffffffffu, v, m);
    if (lane==0) sh[warp]=v;
    __syncthreads();
    int nw = (blockDim.x+31)>>5;
    float t = 0.f;
    #pragma unroll
    for (int i=0;i<8;i++) if (i<nw) t += sh[i];
    return t;
}

// ---------------- rmsnorm over rows of width D ----------------
__global__ void rmsnorm_kernel(const float* __restrict__ in, const float* __restrict__ w,
                               float* __restrict__ out, int D){
    __shared__ float sh[8];
    int row = blockIdx.x;
    const float* xr = in + (size_t)row*D;
    float ss = 0.f;
    for (int d=threadIdx.x; d<D; d+=blockDim.x){ float v=xr[d]; ss += v*v; }
    float tot = block_reduce_sum(ss, sh);
    float scale = rsqrtf(tot/(float)D + 1e-6f);
    for (int d=threadIdx.x; d<D; d+=blockDim.x)
        out[(size_t)row*D + d] = xr[d]*scale*w[d];
}

// ---------------- fp32 SGEMM: C = A(MxK) @ B(KxN) [+ addsrc] ----------------
#define BM 128
#define BN 128
#define BKK 16
#define TM 8
#define TN 8
__global__ void __launch_bounds__(256) sgemm_kernel(
        const float* __restrict__ A, const float* __restrict__ B,
        float* __restrict__ C, const float* __restrict__ addsrc,
        int M, int N, int K){
    __shared__ float As[BKK][BM];
    __shared__ float Bs[BKK][BN];
    int tid = threadIdx.x;
    int bm = blockIdx.y * BM, bn = blockIdx.x * BN;
    int tx = tid & 15, ty = tid >> 4;
    float acc[TM][TN];
    #pragma unroll
    for (int i=0;i<TM;i++)
        #pragma unroll
        for (int j=0;j<TN;j++) acc[i][j]=0.f;

    for (int k0 = 0; k0 < K; k0 += BKK){
        #pragma unroll
        for (int l=0;l<2;l++){
            int idx = tid + l*256;
            int ar = idx >> 2, ak = (idx & 3) << 2;
            float4 av = *(const float4*)&A[(size_t)(bm+ar)*K + k0 + ak];
            As[ak+0][ar]=av.x; As[ak+1][ar]=av.y; As[ak+2][ar]=av.z; As[ak+3][ar]=av.w;
            int br = idx >> 5, bc = (idx & 31) << 2;
            *(float4*)&Bs[br][bc] = *(const float4*)&B[(size_t)(k0+br)*N + bn + bc];
        }
        __syncthreads();
        #pragma unroll
        for (int kk=0; kk<BKK; kk++){
            float a[TM], b[TN];
            #pragma unroll
            for (int i=0;i<TM;i+=4) *(float4*)&a[i] = *(const float4*)&As[kk][ty*TM+i];
            #pragma unroll
            for (int j=0;j<TN;j+=4) *(float4*)&b[j] = *(const float4*)&Bs[kk][tx*TN+j];
            #pragma unroll
            for (int i=0;i<TM;i++)
                #pragma unroll
                for (int j=0;j<TN;j++) acc[i][j] += a[i]*b[j];
        }
        __syncthreads();
    }
    #pragma unroll
    for (int i=0;i<TM;i++){
        int row = bm + ty*TM + i;
        #pragma unroll
        for (int j=0;j<TN;j+=4){
            int col = bn + tx*TN + j;
            float4 r = make_float4(acc[i][j],acc[i][j+1],acc[i][j+2],acc[i][j+3]);
            if (addsrc){
                float4 s = *(const float4*)&addsrc[(size_t)row*N + col];
                r.x+=s.x; r.y+=s.y; r.z+=s.z; r.w+=s.w;
            }
            *(float4*)&C[(size_t)row*N + col] = r;
        }
    }
}

// ---------------- beta / g small-N projections ----------------
__global__ void beta_g_kernel(const float* __restrict__ x, const float* __restrict__ Wb,
        const float* __restrict__ Wa, const float* __restrict__ A_log,
        const float* __restrict__ dt_bias,
        float* __restrict__ beta, float* __restrict__ g){
    int row = blockIdx.x;
    __shared__ float sx[Dd];
    const float* xr = x + (size_t)row*Dd;
    for (int d=threadIdx.x; d<Dd; d+=128) sx[d]=xr[d];
    __syncthreads();
    int warp = threadIdx.x >> 5, lane = threadIdx.x & 31;
    for (int out = warp; out < 24; out += 4){
        float s = 0.f;
        if (out < 16){
            for (int d=lane; d<Dd; d+=32) s += sx[d]*Wb[d*16 + out];
        } else {
            int c = out - 16;
            for (int d=lane; d<Dd; d+=32) s += sx[d]*Wa[d*8 + c];
        }
        #pragma unroll
        for (int m=16;m;m>>=1) s += __shfl_xor_sync(0xffffffffu, s, m);
        if (lane==0){
            if (out<16) beta[(size_t)row*16 + out] = sigmoidf_(s);
            else {
                int h = out-16;
                float v = s + dt_bias[h];
                float sp = v > 20.f ? v : log1pf(expf(v));
                g[(size_t)row*8 + h] = -expf(A_log[h])*sp;
            }
        }
    }
}

// ---------------- causal depthwise conv(K=4) + silu (+ optional l2norm/128) --
__global__ void conv_silu_kernel(const float* __restrict__ pre, const float* __restrict__ w,
                                 float* __restrict__ out, int nch, int do_norm){
    int b = blockIdx.z, t = blockIdx.y;
    int ch = blockIdx.x*128 + threadIdx.x;
    float acc = 0.f;
    #pragma unroll
    for (int i=0;i<4;i++){
        int tt = t - 3 + i;
        if (tt >= 0)
            acc += pre[((size_t)(b*Tt + tt))*nch + ch] * w[ch*4 + i];
    }
    float s = siluf_(acc);
    if (do_norm){
        float ss = s*s;
        #pragma unroll
        for (int m=16;m;m>>=1) ss += __shfl_xor_sync(0xffffffffu, ss, m);
        __shared__ float sw[4];
        if ((threadIdx.x&31)==0) sw[threadIdx.x>>5] = ss;
        __syncthreads();
        float tot = sw[0]+sw[1]+sw[2]+sw[3];
        s *= rsqrtf(tot + 1e-6f);
    }
    out[((size_t)(b*Tt + t))*nch + ch] = s;
}

// ---------------- recurrent gated delta-product scan ----------------
// grid: (DV/32=8, H=8, B=2), 256 threads = 16 dk-groups x 16 v-groups(2 v each)
__global__ void __launch_bounds__(256) scan_kernel(
        const float* __restrict__ q, const float* __restrict__ k,
        const float* __restrict__ v, const float* __restrict__ beta,
        const float* __restrict__ g, float* __restrict__ o){
    int vchunk = blockIdx.x, h = blockIdx.y, b = blockIdx.z;
    int tid = threadIdx.x;
    int dkg = tid & 15;         // 16 groups of 8 dk
    int vg  = tid >> 4;         // 16 groups of 2 v
    int vbase = vchunk*32;
    __shared__ float sQ[144], sK[2][144], sV[2][32], sS[4];
    float S[8][2];
    #pragma unroll
    for (int i=0;i<8;i++){ S[i][0]=0.f; S[i][1]=0.f; }
    const int chq = h*DK;
    const int kb = dkg*9;       // padded base: idx(dk)=dk+(dk>>3)

    for (int t=0;t<Tt;t++){
        size_t bt = (size_t)b*Tt + t;
        if (tid < 128){ int dk=tid; sQ[dk+(dk>>3)] = q[bt*1024 + chq + dk]; }
        { int j = tid>>7, dk = tid&127;
          sK[j][dk+(dk>>3)] = k[(bt*2 + j)*1024 + chq + dk]; }
        if (tid < 64){ int j = tid>>5, vl = tid&31;
          sV[j][vl] = v[(bt*2 + j)*2048 + h*DV + vbase + vl]; }
        if (tid == 0){
            sS[0] = g[bt*8 + h];
            sS[1] = beta[bt*16 + h*2 + 0];
            sS[2] = beta[bt*16 + h*2 + 1];
        }
        __syncthreads();

        float dec = expf(sS[0]);
        #pragma unroll
        for (int i=0;i<8;i++){ S[i][0]*=dec; S[i][1]*=dec; }

        #pragma unroll
        for (int j=0;j<2;j++){
            float kk[8];
            #pragma unroll
            for (int i=0;i<8;i++) kk[i] = sK[j][kb+i];
            float p0=0.f, p1=0.f;
            #pragma unroll
            for (int i=0;i<8;i++){ p0 += kk[i]*S[i][0]; p1 += kk[i]*S[i][1]; }
            #pragma unroll
            for (int m=1;m<16;m<<=1){
                p0 += __shfl_xor_sync(0xffffffffu, p0, m);
                p1 += __shfl_xor_sync(0xffffffffu, p1, m);
            }
            float bj = sS[1+j];
            float d0 = bj*(sV[j][vg*2+0] - p0);
            float d1 = bj*(sV[j][vg*2+1] - p1);
            #pragma unroll
            for (int i=0;i<8;i++){ S[i][0] += kk[i]*d0; S[i][1] += kk[i]*d1; }
        }

        float p0=0.f, p1=0.f;
        #pragma unroll
        for (int i=0;i<8;i++){ float qv = sQ[kb+i]; p0 += qv*S[i][0]; p1 += qv*S[i][1]; }
        #pragma unroll
        for (int m=1;m<16;m<<=1){
            p0 += __shfl_xor_sync(0xffffffffu, p0, m);
            p1 += __shfl_xor_sync(0xffffffffu, p1, m);
        }
        if (dkg == 0){
            size_t ob = bt*2048 + h*DV + vbase + vg*2;
            o[ob]   = p0;
            o[ob+1] = p1;
        }
        __syncthreads();
    }
}

// ---------------- o-norm * silu(gate), in place ----------------
__global__ void ogate_kernel(float* __restrict__ o, const float* __restrict__ gate,
                             const float* __restrict__ onw){
    __shared__ float sh[8];
    int bt = blockIdx.x, h = blockIdx.y, vv = threadIdx.x;
    size_t idx = (size_t)bt*2048 + h*DV + vv;
    float val = o[idx];
    float tot = block_reduce_sum(val*val, sh);
    float scale = rsqrtf(tot/(float)DV + 1e-6f);
    float gt = gate[idx];
    o[idx] = val*scale*onw[vv]*siluf_(gt);
}

// ---------------- swiglu ----------------
__global__ void swiglu_kernel(const float* __restrict__ gu, float* __restrict__ out){
    int i = blockIdx.x*256 + threadIdx.x;
    if (i < BT*INTER){
        int row = i / INTER, c = i % INTER;
        float a  = gu[(size_t)row*(2*INTER) + c];
        float u  = gu[(size_t)row*(2*INTER) + INTER + c];
        out[i] = siluf_(a)*u;
    }
}

// ---------------- launch ----------------
extern "C" void kernel_launch(void* const* d_in, const int* in_sizes, int n_in,
                              void* d_out, int out_size){
    const float* hs         = (const float*)d_in[0];
    const float* attn_nw    = (const float*)d_in[1];
    const float* Wq         = (const float*)d_in[2];
    const float* Wk         = (const float*)d_in[3];
    const float* Wv         = (const float*)d_in[4];
    const float* Wb         = (const float*)d_in[5];
    const float* Wa         = (const float*)d_in[6];
    const float* A_log      = (const float*)d_in[7];
    const float* dt_bias    = (const float*)d_in[8];
    const float* conv_q_w   = (const float*)d_in[9];
    const float* conv_k_w   = (const float*)d_in[10];
    const float* conv_v_w   = (const float*)d_in[11];
    const float* Wg         = (const float*)d_in[12];
    const float* o_norm_w   = (const float*)d_in[13];
    const float* Wo         = (const float*)d_in[14];
    const float* mlp_norm_w = (const float*)d_in[15];
    const float* Wgate      = (const float*)d_in[16];
    const float* Wdown      = (const float*)d_in[17];

    float *x,*qpre,*kpre,*vpre,*qb,*kb,*vb,*gatep,*betab,*gb,*ob,*hid,*yb,*gub,*mlpb;
    cudaGetSymbolAddress((void**)&x,    g_x);
    cudaGetSymbolAddress((void**)&qpre, g_qpre);
    cudaGetSymbolAddress((void**)&kpre, g_kpre);
    cudaGetSymbolAddress((void**)&vpre, g_vpre);
    cudaGetSymbolAddress((void**)&qb,   g_q);
    cudaGetSymbolAddress((void**)&kb,   g_k);
    cudaGetSymbolAddress((void**)&vb,   g_v);
    cudaGetSymbolAddress((void**)&gatep,g_gate);
    cudaGetSymbolAddress((void**)&betab,g_beta);
    cudaGetSymbolAddress((void**)&gb,   g_gdec);
    cudaGetSymbolAddress((void**)&ob,   g_o);
    cudaGetSymbolAddress((void**)&hid,  g_hid);
    cudaGetSymbolAddress((void**)&yb,   g_y);
    cudaGetSymbolAddress((void**)&gub,  g_gu);
    cudaGetSymbolAddress((void**)&mlpb, g_mlp);

    // 1) x = rmsnorm(hidden) * attn_norm_w
    rmsnorm_kernel<<<BT, 256>>>(hs, attn_nw, x, Dd);

    // 2) projections
    sgemm_kernel<<<dim3( 8,32),256>>>(x, Wq, qpre,  nullptr, BT, 1024, 1024);
    sgemm_kernel<<<dim3(16,32),256>>>(x, Wk, kpre,  nullptr, BT, 2048, 1024);
    sgemm_kernel<<<dim3(32,32),256>>>(x, Wv, vpre,  nullptr, BT, 4096, 1024);
    sgemm_kernel<<<dim3(16,32),256>>>(x, Wg, gatep, nullptr, BT, 2048, 1024);
    beta_g_kernel<<<BT,128>>>(x, Wb, Wa, A_log, dt_bias, betab, gb);

    // 3) causal conv + silu (+ l2norm for q,k)
    conv_silu_kernel<<<dim3( 8,Tt,Bb),128>>>(qpre, conv_q_w, qb, 1024, 1);
    conv_silu_kernel<<<dim3(16,Tt,Bb),128>>>(kpre, conv_k_w, kb, 2048, 1);
    conv_silu_kernel<<<dim3(32,Tt,Bb),128>>>(vpre, conv_v_w, vb, 4096, 0);

    // 4) gated delta-product recurrence
    scan_kernel<<<dim3(8,8,2),256>>>(qb, kb, vb, betab, gb, ob);

    // 5) o = rmsnorm(o)*silu(gate), then residual GEMM
    ogate_kernel<<<dim3(BT,Hh),256>>>(ob, gatep, o_norm_w);
    sgemm_kernel<<<dim3( 8,32),256>>>(ob, Wo, hid, hs, BT, 1024, 2048);

    // 6) MLP
    rmsnorm_kernel<<<BT,256>>>(hid, mlp_norm_w, yb, Dd);
    sgemm_kernel<<<dim3(44,32),256>>>(yb, Wgate, gub, nullptr, BT, 2*INTER, 1024);
    swiglu_kernel<<<(BT*INTER+255)/256,256>>>(gub, mlpb);
    sgemm_kernel<<<dim3( 8,32),256>>>(mlpb, Wdown, (float*)d_out, hid, BT, 1024, INTER);
}

// round 3
// speedup vs baseline: 1.8785x; 1.8785x over previous
#include <cuda_runtime.h>
#include <cuda_bf16.h>
#include <math.h>
#include <stdint.h>

// ---------------- problem constants ----------------
#define Bb 2
#define Tt 2048
#define Dd 1024
#define Hh 8
#define DK 128
#define DV 256
#define NH 2
#define INTER 2816
#define BT (Bb*Tt)              // 4096

// ---------------- scratch (device globals; no allocation allowed) ----------
__device__ float g_x   [(size_t)BT*Dd];
__device__ float g_qpre[(size_t)BT*Hh*DK];
__device__ float g_kpre[(size_t)BT*NH*Hh*DK];
__device__ float g_vpre[(size_t)BT*NH*Hh*DV];
__device__ float g_q   [(size_t)BT*Hh*DK];
__device__ float g_k   [(size_t)BT*NH*Hh*DK];
__device__ float g_v   [(size_t)BT*NH*Hh*DV];
__device__ float g_gate[(size_t)BT*Hh*DV];
__device__ float g_beta[(size_t)BT*Hh*NH];
__device__ float g_gdec[(size_t)BT*Hh];
__device__ float g_o   [(size_t)BT*Hh*DV];
__device__ float g_hid [(size_t)BT*Dd];
__device__ float g_y   [(size_t)BT*Dd];
__device__ float g_gu  [(size_t)BT*2*INTER];
__device__ float g_mlp [(size_t)BT*INTER];

// bf16x3 split buffers (activations: [M, 3K]; weights transposed: [N, 3K])
__device__ __nv_bfloat16 g3_x   [(size_t)BT*3*1024];
__device__ __nv_bfloat16 g3_y   [(size_t)BT*3*1024];
__device__ __nv_bfloat16 g3_o   [(size_t)BT*3*2048];
__device__ __nv_bfloat16 g3_mlp [(size_t)BT*3*2816];
__device__ __nv_bfloat16 g3_Wq   [(size_t)1024*3*1024];
__device__ __nv_bfloat16 g3_Wk   [(size_t)2048*3*1024];
__device__ __nv_bfloat16 g3_Wv   [(size_t)4096*3*1024];
__device__ __nv_bfloat16 g3_Wg   [(size_t)2048*3*1024];
__device__ __nv_bfloat16 g3_Wo   [(size_t)1024*3*2048];
__device__ __nv_bfloat16 g3_Wgate[(size_t)5632*3*1024];
__device__ __nv_bfloat16 g3_Wdown[(size_t)1024*3*2816];

// ---------------- helpers ----------------
__device__ __forceinline__ uint32_t smem_u32(const void* p){
    uint32_t a;
    asm("{ .reg .u64 t; cvta.to.shared.u64 t, %1; cvt.u32.u64 %0, t; }" : "=r"(a) : "l"(p));
    return a;
}
__device__ __forceinline__ void cp16(uint32_t s, const void* g){
    asm volatile("cp.async.cg.shared.global [%0], [%1], 16;" :: "r"(s), "l"(g) : "memory");
}
__device__ __forceinline__ void mma16816(float* d, const uint32_t* a, const uint32_t* b){
    asm volatile("mma.sync.aligned.m16n8k16.row.col.f32.bf16.bf16.f32 "
        "{%0,%1,%2,%3}, {%4,%5,%6,%7}, {%8,%9}, {%0,%1,%2,%3};"
        : "+f"(d[0]), "+f"(d[1]), "+f"(d[2]), "+f"(d[3])
        : "r"(a[0]), "r"(a[1]), "r"(a[2]), "r"(a[3]), "r"(b[0]), "r"(b[1]));
}
__device__ __forceinline__ float sigmoidf_(float x){ return 1.f/(1.f+expf(-x)); }
__device__ __forceinline__ float siluf_(float x){ return x*sigmoidf_(x); }

__device__ __forceinline__ float block_reduce_sum(float v, float* sh){
    int lane = threadIdx.x & 31, warp = threadIdx.x >> 5;
    #pragma unroll
    for (int m=16;m;m>>=1) v += __shfl_xor_sync(0xffffffffu, v, m);
    if (lane==0) sh[warp]=v;
    __syncthreads();
    int nw = (blockDim.x+31)>>5;
    float t = 0.f;
    #pragma unroll
    for (int i=0;i<8;i++) if (i<nw) t += sh[i];
    return t;
}

// ---------------- rmsnorm ----------------
__global__ void rmsnorm_kernel(const float* __restrict__ in, const float* __restrict__ w,
                               float* __restrict__ out, int D){
    __shared__ float sh[8];
    int row = blockIdx.x;
    const float* xr = in + (size_t)row*D;
    float ss = 0.f;
    for (int d=threadIdx.x; d<D; d+=blockDim.x){ float v=xr[d]; ss += v*v; }
    float tot = block_reduce_sum(ss, sh);
    float scale = rsqrtf(tot/(float)D + 1e-6f);
    for (int d=threadIdx.x; d<D; d+=blockDim.x)
        out[(size_t)row*D + d] = xr[d]*scale*w[d];
}

// ---------------- bf16x3 split conversions ----------------
// activation [M,K] fp32 -> [M,3K] bf16 : segs [hi, hi, lo]
__global__ void a3_kernel(const float* __restrict__ A, __nv_bfloat16* __restrict__ A3, int K){
    int m = blockIdx.y;
    int k = blockIdx.x*256 + threadIdx.x;
    float v = A[(size_t)m*K + k];
    __nv_bfloat16 hi = __float2bfloat16(v);
    float r = v - __bfloat162float(hi);
    __nv_bfloat16 lo = __float2bfloat16(r);
    size_t base = (size_t)m*3*K;
    A3[base + k]       = hi;
    A3[base + K + k]   = hi;
    A3[base + 2*K + k] = lo;
}
// weight [K,N] fp32 -> transposed [N,3K] bf16 : segs [hi, lo, hi]
__global__ void w3_kernel(const float* __restrict__ W, __nv_bfloat16* __restrict__ B3, int K, int N){
    __shared__ float tile[32][33];
    int n0 = blockIdx.x*32, k0 = blockIdx.y*32;
    int tx = threadIdx.x & 31, ty = threadIdx.x >> 5;
    #pragma unroll
    for (int i=0;i<4;i++)
        tile[ty + i*8][tx] = W[(size_t)(k0 + ty + i*8)*N + n0 + tx];
    __syncthreads();
    #pragma unroll
    for (int i=0;i<4;i++){
        int n = n0 + ty + i*8;
        float v = tile[tx][ty + i*8];           // = W[k0+tx][n]
        __nv_bfloat16 hi = __float2bfloat16(v);
        float r = v - __bfloat162float(hi);
        __nv_bfloat16 lo = __float2bfloat16(r);
        size_t base = (size_t)n*3*K;
        B3[base + k0 + tx]         = hi;
        B3[base + K + k0 + tx]     = lo;
        B3[base + 2*K + k0 + tx]   = hi;
    }
}

// ---------------- bf16 mma.sync GEMM: C[M,N] = A3[M,Kp] . B3[N,Kp]^T (+add) --
// 128x128 tile, BK=32, 3-stage cp.async pipeline, 8 warps (4x2), 32x64/warp
#define BKg   32
#define STG   3
#define ROWB  80            // 64B data + 16B pad per 32-bf16 row
#define ATILE (128*ROWB)    // 10240
#define STILE (2*ATILE)     // 20480 per stage
#define GEMM_SMEM (STG*STILE)

__global__ void __launch_bounds__(256) mma_gemm(
        const __nv_bfloat16* __restrict__ A, const __nv_bfloat16* __restrict__ B,
        float* __restrict__ C, const float* __restrict__ addsrc,
        int M, int N, int Kp){
    extern __shared__ char smem[];
    int tid = threadIdx.x;
    int bm = blockIdx.y*128, bn = blockIdx.x*128;
    uint32_t sbase = smem_u32(smem);

    int lane = tid & 31, wid = tid >> 5;
    int warpM = wid >> 1, warpN = wid & 1;
    int g = lane >> 2, tg = lane & 3;

    const char* gAb = (const char*)(A + (size_t)bm*Kp);
    const char* gBb = (const char*)(B + (size_t)bn*Kp);
    int ldr = tid >> 2, ldc = tid & 3;          // 256 thr -> rows 0..63, chunk 0..3
    const int nch = Kp / BKg;

    // issue chunk -> slot
    #define ISSUE(chunk, slot) do { \
        uint32_t sA_ = sbase + (slot)*STILE; \
        uint32_t sB_ = sA_ + ATILE; \
        size_t kof = (size_t)(chunk)*BKg*2; \
        _Pragma("unroll") \
        for (int i_=0;i_<2;i_++){ \
            int row_ = ldr + i_*64; \
            cp16(sA_ + row_*ROWB + ldc*16, gAb + (size_t)row_*Kp*2 + kof + ldc*16); \
            cp16(sB_ + row_*ROWB + ldc*16, gBb + (size_t)row_*Kp*2 + kof + ldc*16); \
        } \
        asm volatile("cp.async.commit_group;" ::: "memory"); \
    } while(0)

    float acc[2][8][4];
    #pragma unroll
    for (int mt=0;mt<2;mt++)
        #pragma unroll
        for (int nt=0;nt<8;nt++)
            #pragma unroll
            for (int i=0;i<4;i++) acc[mt][nt][i]=0.f;

    ISSUE(0,0);
    ISSUE(1,1);

    for (int c=0; c<nch; c++){
        asm volatile("cp.async.wait_group 1;" ::: "memory");
        __syncthreads();
        if (c+2 < nch) ISSUE(c+2, (c+2)%STG);

        uint32_t sA = sbase + (c%STG)*STILE;
        uint32_t sB = sA + ATILE;
        #pragma unroll
        for (int ks=0; ks<2; ks++){
            uint32_t a[2][4], b[8][2];
            #pragma unroll
            for (int mt=0;mt<2;mt++){
                uint32_t base = sA + (uint32_t)((warpM*32 + mt*16 + g)*ROWB + ks*32 + tg*4);
                asm volatile("ld.shared.b32 %0,[%1];" : "=r"(a[mt][0]) : "r"(base));
                asm volatile("ld.shared.b32 %0,[%1];" : "=r"(a[mt][1]) : "r"(base + 8*ROWB));
                asm volatile("ld.shared.b32 %0,[%1];" : "=r"(a[mt][2]) : "r"(base + 16));
                asm volatile("ld.shared.b32 %0,[%1];" : "=r"(a[mt][3]) : "r"(base + 8*ROWB + 16));
            }
            #pragma unroll
            for (int nt=0;nt<8;nt++){
                uint32_t base = sB + (uint32_t)((warpN*64 + nt*8 + g)*ROWB + ks*32 + tg*4);
                asm volatile("ld.shared.b32 %0,[%1];" : "=r"(b[nt][0]) : "r"(base));
                asm volatile("ld.shared.b32 %0,[%1];" : "=r"(b[nt][1]) : "r"(base + 16));
            }
            #pragma unroll
            for (int mt=0;mt<2;mt++)
                #pragma unroll
                for (int nt=0;nt<8;nt++)
                    mma16816(acc[mt][nt], a[mt], b[nt]);
        }
        __syncthreads();
    }

    // epilogue
    #pragma unroll
    for (int mt=0;mt<2;mt++){
        int r0 = bm + warpM*32 + mt*16 + g;
        #pragma unroll
        for (int nt=0;nt<8;nt++){
            int col = bn + warpN*64 + nt*8 + tg*2;
            float2 v0 = make_float2(acc[mt][nt][0], acc[mt][nt][1]);
            float2 v1 = make_float2(acc[mt][nt][2], acc[mt][nt][3]);
            if (addsrc){
                float2 s0 = *(const float2*)&addsrc[(size_t)r0*N + col];
                float2 s1 = *(const float2*)&addsrc[(size_t)(r0+8)*N + col];
                v0.x+=s0.x; v0.y+=s0.y; v1.x+=s1.x; v1.y+=s1.y;
            }
            *(float2*)&C[(size_t)r0*N + col] = v0;
            *(float2*)&C[(size_t)(r0+8)*N + col] = v1;
        }
    }
    #undef ISSUE
}

// ---------------- beta / g small-N projections ----------------
__global__ void beta_g_kernel(const float* __restrict__ x, const float* __restrict__ Wb,
        const float* __restrict__ Wa, const float* __restrict__ A_log,
        const float* __restrict__ dt_bias,
        float* __restrict__ beta, float* __restrict__ g){
    int row = blockIdx.x;
    __shared__ float sx[Dd];
    const float* xr = x + (size_t)row*Dd;
    for (int d=threadIdx.x; d<Dd; d+=128) sx[d]=xr[d];
    __syncthreads();
    int warp = threadIdx.x >> 5, lane = threadIdx.x & 31;
    for (int out = warp; out < 24; out += 4){
        float s = 0.f;
        if (out < 16){
            for (int d=lane; d<Dd; d+=32) s += sx[d]*Wb[d*16 + out];
        } else {
            int c = out - 16;
            for (int d=lane; d<Dd; d+=32) s += sx[d]*Wa[d*8 + c];
        }
        #pragma unroll
        for (int m=16;m;m>>=1) s += __shfl_xor_sync(0xffffffffu, s, m);
        if (lane==0){
            if (out<16) beta[(size_t)row*16 + out] = sigmoidf_(s);
            else {
                int h = out-16;
                float v = s + dt_bias[h];
                float sp = v > 20.f ? v : log1pf(expf(v));
                g[(size_t)row*8 + h] = -expf(A_log[h])*sp;
            }
        }
    }
}

// ---------------- causal conv(K=4) + silu (+ optional l2norm/128) ----------
__global__ void conv_silu_kernel(const float* __restrict__ pre, const float* __restrict__ w,
                                 float* __restrict__ out, int nch, int do_norm){
    int b = blockIdx.z, t = blockIdx.y;
    int ch = blockIdx.x*128 + threadIdx.x;
    float acc = 0.f;
    #pragma unroll
    for (int i=0;i<4;i++){
        int tt = t - 3 + i;
        if (tt >= 0)
            acc += pre[((size_t)(b*Tt + tt))*nch + ch] * w[ch*4 + i];
    }
    float s = siluf_(acc);
    if (do_norm){
        float ss = s*s;
        #pragma unroll
        for (int m=16;m;m>>=1) ss += __shfl_xor_sync(0xffffffffu, ss, m);
        __shared__ float sw[4];
        if ((threadIdx.x&31)==0) sw[threadIdx.x>>5] = ss;
        __syncthreads();
        float tot = sw[0]+sw[1]+sw[2]+sw[3];
        s *= rsqrtf(tot + 1e-6f);
    }
    out[((size_t)(b*Tt + t))*nch + ch] = s;
}

// ---------------- recurrent gated delta-product scan (with prefetch) -------
__global__ void __launch_bounds__(256) scan_kernel(
        const float* __restrict__ q, const float* __restrict__ k,
        const float* __restrict__ v, const float* __restrict__ beta,
        const float* __restrict__ g, float* __restrict__ o){
    int vchunk = blockIdx.x, h = blockIdx.y, b = blockIdx.z;
    int tid = threadIdx.x;
    int dkg = tid & 15;
    int vg  = tid >> 4;
    int vbase = vchunk*32;
    __shared__ float sQ[144], sK[2][144], sV[2][32], sS[4];
    float S[8][2];
    #pragma unroll
    for (int i=0;i<8;i++){ S[i][0]=0.f; S[i][1]=0.f; }
    const int chq = h*DK;
    const int kb = dkg*9;

    float rq=0.f, rk=0.f, rv=0.f, rs=0.f;
    {
        size_t bt = (size_t)b*Tt;
        if (tid < 128) rq = q[bt*1024 + chq + tid];
        rk = k[(bt*2 + (tid>>7))*1024 + chq + (tid&127)];
        if (tid < 64) rv = v[(bt*2 + (tid>>5))*2048 + h*DV + vbase + (tid&31)];
        if (tid == 0) rs = g[bt*8 + h];
        else if (tid == 1) rs = beta[bt*16 + h*2 + 0];
        else if (tid == 2) rs = beta[bt*16 + h*2 + 1];
    }

    for (int t=0;t<Tt;t++){
        if (tid < 128) sQ[tid + (tid>>3)] = rq;
        { int dk = tid&127; sK[tid>>7][dk + (dk>>3)] = rk; }
        if (tid < 64) sV[tid>>5][tid&31] = rv;
        if (tid < 3)  sS[tid] = rs;
        __syncthreads();

        if (t+1 < Tt){
            size_t bt = (size_t)b*Tt + t + 1;
            if (tid < 128) rq = q[bt*1024 + chq + tid];
            rk = k[(bt*2 + (tid>>7))*1024 + chq + (tid&127)];
            if (tid < 64) rv = v[(bt*2 + (tid>>5))*2048 + h*DV + vbase + (tid&31)];
            if (tid == 0) rs = g[bt*8 + h];
            else if (tid == 1) rs = beta[bt*16 + h*2 + 0];
            else if (tid == 2) rs = beta[bt*16 + h*2 + 1];
        }

        float dec = expf(sS[0]);
        #pragma unroll
        for (int i=0;i<8;i++){ S[i][0]*=dec; S[i][1]*=dec; }

        #pragma unroll
        for (int j=0;j<2;j++){
            float kk[8];
            #pragma unroll
            for (int i=0;i<8;i++) kk[i] = sK[j][kb+i];
            float p0=0.f, p1=0.f;
            #pragma unroll
            for (int i=0;i<8;i++){ p0 += kk[i]*S[i][0]; p1 += kk[i]*S[i][1]; }
            #pragma unroll
            for (int m=1;m<16;m<<=1){
                p0 += __shfl_xor_sync(0xffffffffu, p0, m);
                p1 += __shfl_xor_sync(0xffffffffu, p1, m);
            }
            float bj = sS[1+j];
            float d0 = bj*(sV[j][vg*2+0] - p0);
            float d1 = bj*(sV[j][vg*2+1] - p1);
            #pragma unroll
            for (int i=0;i<8;i++){ S[i][0] += kk[i]*d0; S[i][1] += kk[i]*d1; }
        }

        float p0=0.f, p1=0.f;
        #pragma unroll
        for (int i=0;i<8;i++){ float qv = sQ[kb+i]; p0 += qv*S[i][0]; p1 += qv*S[i][1]; }
        #pragma unroll
        for (int m=1;m<16;m<<=1){
            p0 += __shfl_xor_sync(0xffffffffu, p0, m);
            p1 += __shfl_xor_sync(0xffffffffu, p1, m);
        }
        if (dkg == 0){
            size_t ob = ((size_t)b*Tt + t)*2048 + h*DV + vbase + vg*2;
            o[ob]   = p0;
            o[ob+1] = p1;
        }
        __syncthreads();
    }
}

// ---------------- o-norm * silu(gate), in place ----------------
__global__ void ogate_kernel(float* __restrict__ o, const float* __restrict__ gate,
                             const float* __restrict__ onw){
    __shared__ float sh[8];
    int bt = blockIdx.x, h = blockIdx.y, vv = threadIdx.x;
    size_t idx = (size_t)bt*2048 + h*DV + vv;
    float val = o[idx];
    float tot = block_reduce_sum(val*val, sh);
    float scale = rsqrtf(tot/(float)DV + 1e-6f);
    float gt = gate[idx];
    o[idx] = val*scale*onw[vv]*siluf_(gt);
}

// ---------------- swiglu ----------------
__global__ void swiglu_kernel(const float* __restrict__ gu, float* __restrict__ out){
    int i = blockIdx.x*256 + threadIdx.x;
    if (i < BT*INTER){
        int row = i / INTER, c = i % INTER;
        float a  = gu[(size_t)row*(2*INTER) + c];
        float u  = gu[(size_t)row*(2*INTER) + INTER + c];
        out[i] = siluf_(a)*u;
    }
}

// ---------------- launch ----------------
extern "C" void kernel_launch(void* const* d_in, const int* in_sizes, int n_in,
                              void* d_out, int out_size){
    const float* hs         = (const float*)d_in[0];
    const float* attn_nw    = (const float*)d_in[1];
    const float* Wq         = (const float*)d_in[2];
    const float* Wk         = (const float*)d_in[3];
    const float* Wv         = (const float*)d_in[4];
    const float* Wb         = (const float*)d_in[5];
    const float* Wa         = (const float*)d_in[6];
    const float* A_log      = (const float*)d_in[7];
    const float* dt_bias    = (const float*)d_in[8];
    const float* conv_q_w   = (const float*)d_in[9];
    const float* conv_k_w   = (const float*)d_in[10];
    const float* conv_v_w   = (const float*)d_in[11];
    const float* Wg         = (const float*)d_in[12];
    const float* o_norm_w   = (const float*)d_in[13];
    const float* Wo         = (const float*)d_in[14];
    const float* mlp_norm_w = (const float*)d_in[15];
    const float* Wgate      = (const float*)d_in[16];
    const float* Wdown      = (const float*)d_in[17];

    float *x,*qpre,*kpre,*vpre,*qb,*kb,*vb,*gatep,*betab,*gb,*ob,*hid,*yb,*gub,*mlpb;
    cudaGetSymbolAddress((void**)&x,    g_x);
    cudaGetSymbolAddress((void**)&qpre, g_qpre);
    cudaGetSymbolAddress((void**)&kpre, g_kpre);
    cudaGetSymbolAddress((void**)&vpre, g_vpre);
    cudaGetSymbolAddress((void**)&qb,   g_q);
    cudaGetSymbolAddress((void**)&kb,   g_k);
    cudaGetSymbolAddress((void**)&vb,   g_v);
    cudaGetSymbolAddress((void**)&gatep,g_gate);
    cudaGetSymbolAddress((void**)&betab,g_beta);
    cudaGetSymbolAddress((void**)&gb,   g_gdec);
    cudaGetSymbolAddress((void**)&ob,   g_o);
    cudaGetSymbolAddress((void**)&hid,  g_hid);
    cudaGetSymbolAddress((void**)&yb,   g_y);
    cudaGetSymbolAddress((void**)&gub,  g_gu);
    cudaGetSymbolAddress((void**)&mlpb, g_mlp);

    __nv_bfloat16 *x3,*y3,*o3,*mlp3,*wq3,*wk3,*wv3,*wg3,*wo3,*wgate3,*wdown3;
    cudaGetSymbolAddress((void**)&x3,    g3_x);
    cudaGetSymbolAddress((void**)&y3,    g3_y);
    cudaGetSymbolAddress((void**)&o3,    g3_o);
    cudaGetSymbolAddress((void**)&mlp3,  g3_mlp);
    cudaGetSymbolAddress((void**)&wq3,   g3_Wq);
    cudaGetSymbolAddress((void**)&wk3,   g3_Wk);
    cudaGetSymbolAddress((void**)&wv3,   g3_Wv);
    cudaGetSymbolAddress((void**)&wg3,   g3_Wg);
    cudaGetSymbolAddress((void**)&wo3,   g3_Wo);
    cudaGetSymbolAddress((void**)&wgate3,g3_Wgate);
    cudaGetSymbolAddress((void**)&wdown3,g3_Wdown);

    cudaFuncSetAttribute(mma_gemm, cudaFuncAttributeMaxDynamicSharedMemorySize, GEMM_SMEM);

    // weight conversions (independent of activations)
    w3_kernel<<<dim3( 32,32),256>>>(Wq,    wq3,    1024, 1024);
    w3_kernel<<<dim3( 64,32),256>>>(Wk,    wk3,    1024, 2048);
    w3_kernel<<<dim3(128,32),256>>>(Wv,    wv3,    1024, 4096);
    w3_kernel<<<dim3( 64,32),256>>>(Wg,    wg3,    1024, 2048);
    w3_kernel<<<dim3( 32,64),256>>>(Wo,    wo3,    2048, 1024);
    w3_kernel<<<dim3(176,32),256>>>(Wgate, wgate3, 1024, 5632);
    w3_kernel<<<dim3( 32,88),256>>>(Wdown, wdown3, 2816, 1024);

    // 1) x = rmsnorm(hidden)
    rmsnorm_kernel<<<BT, 256>>>(hs, attn_nw, x, Dd);
    a3_kernel<<<dim3(4,BT),256>>>(x, x3, 1024);

    // 2) projections (tensor-core mma.sync)
    mma_gemm<<<dim3( 8,32),256,GEMM_SMEM>>>(x3, wq3, qpre,  nullptr, BT, 1024, 3072);
    mma_gemm<<<dim3(16,32),256,GEMM_SMEM>>>(x3, wk3, kpre,  nullptr, BT, 2048, 3072);
    mma_gemm<<<dim3(32,32),256,GEMM_SMEM>>>(x3, wv3, vpre,  nullptr, BT, 4096, 3072);
    mma_gemm<<<dim3(16,32),256,GEMM_SMEM>>>(x3, wg3, gatep, nullptr, BT, 2048, 3072);
    beta_g_kernel<<<BT,128>>>(x, Wb, Wa, A_log, dt_bias, betab, gb);

    // 3) causal conv + silu (+ l2norm for q,k)
    conv_silu_kernel<<<dim3( 8,Tt,Bb),128>>>(qpre, conv_q_w, qb, 1024, 1);
    conv_silu_kernel<<<dim3(16,Tt,Bb),128>>>(kpre, conv_k_w, kb, 2048, 1);
    conv_silu_kernel<<<dim3(32,Tt,Bb),128>>>(vpre, conv_v_w, vb, 4096, 0);

    // 4) gated delta-product recurrence
    scan_kernel<<<dim3(8,8,2),256>>>(qb, kb, vb, betab, gb, ob);

    // 5) o = rmsnorm(o)*silu(gate), then residual GEMM
    ogate_kernel<<<dim3(BT,Hh),256>>>(ob, gatep, o_norm_w);
    a3_kernel<<<dim3(8,BT),256>>>(ob, o3, 2048);
    mma_gemm<<<dim3( 8,32),256,GEMM_SMEM>>>(o3, wo3, hid, hs, BT, 1024, 6144);

    // 6) MLP
    rmsnorm_kernel<<<BT,256>>>(hid, mlp_norm_w, yb, Dd);
    a3_kernel<<<dim3(4,BT),256>>>(yb, y3, 1024);
    mma_gemm<<<dim3(44,32),256,GEMM_SMEM>>>(y3, wgate3, gub, nullptr, BT, 2*INTER, 3072);
    swiglu_kernel<<<(BT*INTER+255)/256,256>>>(gub, mlpb);
    a3_kernel<<<dim3(11,BT),256>>>(mlpb, mlp3, 2816);
    mma_gemm<<<dim3( 8,32),256,GEMM_SMEM>>>(mlp3, wdown3, (float*)d_out, hid, BT, 1024, 8448);
}